// round 15
// baseline (speedup 1.0000x reference)
#include <cuda_runtime.h>
#include <cuda_bf16.h>
#include <cstdint>

#define WINDOW 512
#define NMETA  4
#define BM     64
#define NTH    128
#define QSTR   4096
#define KSTR   1024
#define SCALE  0.08838834764831845f

// smem: Q hi/lo [64][256B] + two KV buffers (KH,KL,VH,VL each [32][256B])
#define SM_QH  0
#define SM_QL  16384
#define SM_BUF 32768
#define BUF_SZ 32768
#define KOFF_L 8192
#define VOFF_H 16384
#define VOFF_L 24576
#define SMEM_BYTES 98304

// pre-converted K/V scratch: [8 kv-heads][2048 rows][256 B], smem-identical layout
__device__ __align__(16) char g_KH[8 * 2048 * 256];
__device__ __align__(16) char g_KL[8 * 2048 * 256];
__device__ __align__(16) char g_VH[8 * 2048 * 256];
__device__ __align__(16) char g_VL[8 * 2048 * 256];

__device__ __forceinline__ uint32_t s2u(const void* p){
    uint32_t a;
    asm("{ .reg .u64 t; cvta.to.shared.u64 t, %1; cvt.u32.u64 %0, t; }":"=r"(a):"l"(p));
    return a;
}
__device__ __forceinline__ uint32_t swoff(int row, int col){
    return (uint32_t)(row * 256 + (((col >> 3) ^ (row & 7)) << 4));
}
__device__ __forceinline__ void split2(float a, float b, uint32_t& hp, uint32_t& lp){
    __nv_bfloat16 ah = __float2bfloat16(a), bh = __float2bfloat16(b);
    __nv_bfloat16 al = __float2bfloat16(a - __bfloat162float(ah));
    __nv_bfloat16 bl = __float2bfloat16(b - __bfloat162float(bh));
    hp = (uint32_t)__bfloat16_as_ushort(ah) | ((uint32_t)__bfloat16_as_ushort(bh) << 16);
    lp = (uint32_t)__bfloat16_as_ushort(al) | ((uint32_t)__bfloat16_as_ushort(bl) << 16);
}
__device__ __forceinline__ void ldsm4(uint32_t a, uint32_t r[4]){
    asm volatile("ldmatrix.sync.aligned.m8n8.x4.shared.b16 {%0,%1,%2,%3},[%4];"
        : "=r"(r[0]), "=r"(r[1]), "=r"(r[2]), "=r"(r[3]) : "r"(a));
}
__device__ __forceinline__ void ldsm4t(uint32_t a, uint32_t r[4]){
    asm volatile("ldmatrix.sync.aligned.m8n8.x4.trans.shared.b16 {%0,%1,%2,%3},[%4];"
        : "=r"(r[0]), "=r"(r[1]), "=r"(r[2]), "=r"(r[3]) : "r"(a));
}
__device__ __forceinline__ void mma16816(float d[4], const uint32_t a[4], const uint32_t b[2]){
    asm volatile("mma.sync.aligned.m16n8k16.row.col.f32.bf16.bf16.f32 "
        "{%0,%1,%2,%3},{%4,%5,%6,%7},{%8,%9},{%0,%1,%2,%3};"
        : "+f"(d[0]), "+f"(d[1]), "+f"(d[2]), "+f"(d[3])
        : "r"(a[0]), "r"(a[1]), "r"(a[2]), "r"(a[3]), "r"(b[0]), "r"(b[1]));
}
#define CPA(dst, src) asm volatile("cp.async.cg.shared.global [%0],[%1],16;"::"r"(dst),"l"(src):"memory")
#define CPC()  asm volatile("cp.async.commit_group;":::"memory")
#define CPW0() asm volatile("cp.async.wait_group 0;":::"memory")

// ---- prepass: K/V fp32 -> bf16 hi/lo scratch in swizzled layout
__global__ __launch_bounds__(256)
void prep_kv(const float* __restrict__ K, const float* __restrict__ V)
{
    int idx = blockIdx.x * 256 + threadIdx.x;
    int c2 = idx & 63;
    int n  = (idx >> 6) & 2047;
    int kh = idx >> 17;
    int c  = c2 * 2;
    const float2 k2 = *(const float2*)(K + (size_t)n * KSTR + kh * 128 + c);
    const float2 v2 = *(const float2*)(V + (size_t)n * KSTR + kh * 128 + c);
    size_t off = ((size_t)kh * 2048 + n) * 256
               + (uint32_t)((((c >> 3) ^ (n & 7)) << 4) + (c & 7) * 2);
    uint32_t hp, lp;
    split2(k2.x, k2.y, hp, lp);
    *(uint32_t*)(g_KH + off) = hp; *(uint32_t*)(g_KL + off) = lp;
    split2(v2.x, v2.y, hp, lp);
    *(uint32_t*)(g_VH + off) = hp; *(uint32_t*)(g_VL + off) = lp;
}

__global__ __launch_bounds__(NTH, 2)
void swa_mma_kernel(const float* __restrict__ Q, float* __restrict__ O)
{
    extern __shared__ char smp[];
    const uint32_t sb = s2u(smp);

    const int tid = threadIdx.x, wid = tid >> 5, lane = tid & 31;
    const int h = blockIdx.y, kh = h >> 2;
    const int i0 = ((int)gridDim.x - 1 - (int)blockIdx.x) * BM;  // heavy blocks first

    const int m0 = wid * 16;
    const int r  = lane >> 2;
    const int c2 = (lane & 3) * 2;
    const int lo_m = i0 + m0;           // warp strip's lowest q row

    const int t_lo = (i0 > WINDOW) ? ((i0 - WINDOW) >> 5) : 0;
    const int t_hi = (i0 + BM - 1) >> 5;
    const int ntiles = (t_lo == 0) ? (t_hi + 1) : (t_hi - t_lo + 2);

    auto stage = [&](int tx){
        const int t  = (t_lo == 0) ? tx : ((tx == 0) ? 0 : (t_lo + tx - 1));
        const int j0 = t << 5;
        const bool meta = (t == 0) && (t_lo >= 1);
        const size_t base = ((size_t)kh * 2048 + j0) * 256;
        const uint32_t db = sb + SM_BUF + (uint32_t)(tx & 1) * BUF_SZ;
        const int ng = meta ? 256 : 512;
        for (int g = tid; g < ng; g += NTH) {
            uint32_t go = (uint32_t)g * 16;
            CPA(db + go,          g_KH + base + go);
            CPA(db + KOFF_L + go, g_KL + base + go);
            CPA(db + VOFF_H + go, g_VH + base + go);
            CPA(db + VOFF_L + go, g_VL + base + go);
        }
        CPC();
    };

    stage(0);   // overlap tile-0 prefetch with Q staging

    // ---- stage Q -> bf16 hi/lo (swizzled [m][d])
    {
        const float4* Q4 = (const float4*)(Q + (size_t)i0 * QSTR + h * 128);
        #pragma unroll
        for (int it = 0; it < 16; it++) {
            int e = tid + it * NTH, m = e >> 5, c4 = e & 31, d = c4 * 4;
            float4 q = Q4[(size_t)m * (QSTR / 4) + c4];
            uint32_t h01, l01, h23, l23;
            split2(q.x, q.y, h01, l01); split2(q.z, q.w, h23, l23);
            uint32_t off = swoff(m, d) + (uint32_t)((d & 7) * 2);
            *(uint2*)(smp + SM_QH + off) = make_uint2(h01, h23);
            *(uint2*)(smp + SM_QL + off) = make_uint2(l01, l23);
        }
    }
    __syncthreads();

    // ---- hoist Q fragments into registers (once)
    uint32_t qh[8][4], ql[8][4];
    {
        const int ar = m0 + (lane & 7) + (lane & 8);
        #pragma unroll
        for (int ks = 0; ks < 8; ks++) {
            const int ac = ks * 16 + ((lane & 16) >> 1);
            ldsm4(sb + SM_QH + swoff(ar, ac), qh[ks]);
            ldsm4(sb + SM_QL + swoff(ar, ac), ql[ks]);
        }
    }

    float l0 = 0.f, l1 = 0.f;           // per-lane partial row sums (reduced once at end)
    float o[16][4];
    #pragma unroll
    for (int dt = 0; dt < 16; dt++)
        #pragma unroll
        for (int e = 0; e < 4; e++) o[dt][e] = 0.f;

    for (int tix = 0; tix < ntiles; tix++) {
        const int t  = (t_lo == 0) ? tix : ((tix == 0) ? 0 : (t_lo + tix - 1));
        const int j0 = t << 5;
        const bool meta = (t == 0) && (t_lo >= 1);

        CPW0();                          // tile tix's data landed
        __syncthreads();                 // all warps done reading buf[(tix-1)&1]
        if (tix + 1 < ntiles) stage(tix + 1);

        const uint32_t db = sb + SM_BUF + (uint32_t)(tix & 1) * BUF_SZ;

        // two-sided window/causal block skip. Tile t==0 holds the sink
        // columns (j<NMETA), which are window-exempt -> never lower-skip it.
        const int dcl = lo_m + 15 - j0;
        int ntmin, ntmax, kkmin, kkmax;
        if (meta) { ntmin = 0; ntmax = 1; kkmin = 0; kkmax = 1; }
        else {
            ntmax = min(4, max(0, (dcl >> 3) + 1));
            kkmax = min(2, max(0, (dcl >> 4) + 1));
            if (t == 0) { ntmin = 0; kkmin = 0; }
            else {
                ntmin = max(0, (lo_m - WINDOW - j0) >> 3);
                kkmin = max(0, (lo_m - WINDOW - j0) >> 4);
            }
        }

        // ---- QK^T: S = Qh*Kh + Ql*Kh + Qh*Kl  (x4 ldmatrix: 2 n-tiles per load)
        float s[4][4];
        #pragma unroll
        for (int nt = 0; nt < 4; nt++)
            #pragma unroll
            for (int e = 0; e < 4; e++) s[nt][e] = 0.f;

        #pragma unroll
        for (int ks = 0; ks < 8; ks++) {
            const int bc = ks * 16 + (lane & 8);
            for (int nt = ntmin; nt < ntmax; nt += 2) {
                const int br = (nt + (lane >> 4)) * 8 + (lane & 7);
                uint32_t bh[4], bl[4];
                ldsm4(db + swoff(br, bc), bh);
                ldsm4(db + KOFF_L + swoff(br, bc), bl);
                mma16816(s[nt], qh[ks], bh);
                mma16816(s[nt], ql[ks], bh);
                mma16816(s[nt], qh[ks], bl);
                if (nt + 1 < ntmax) {
                    mma16816(s[nt + 1], qh[ks], bh + 2);
                    mma16816(s[nt + 1], ql[ks], bh + 2);
                    mma16816(s[nt + 1], qh[ks], bl + 2);
                }
            }
        }

        // ---- mask + static-max softmax: p = exp(s*scale)
        {
            const int i_r0 = lo_m + r, i_r1 = i_r0 + 8;
            for (int nt = ntmin; nt < ntmax; nt++) {
                const int jb = j0 + nt * 8 + c2;
                bool ok0 = (i_r0 >= jb)     && (((i_r0 - jb)     <= WINDOW) || (jb     < NMETA));
                bool ok1 = (i_r0 >= jb + 1) && (((i_r0 - jb - 1) <= WINDOW) || (jb + 1 < NMETA));
                bool ok2 = (i_r1 >= jb)     && (((i_r1 - jb)     <= WINDOW) || (jb     < NMETA));
                bool ok3 = (i_r1 >= jb + 1) && (((i_r1 - jb - 1) <= WINDOW) || (jb + 1 < NMETA));
                float p0 = ok0 ? __expf(s[nt][0] * SCALE) : 0.f;
                float p1 = ok1 ? __expf(s[nt][1] * SCALE) : 0.f;
                float p2 = ok2 ? __expf(s[nt][2] * SCALE) : 0.f;
                float p3 = ok3 ? __expf(s[nt][3] * SCALE) : 0.f;
                s[nt][0] = p0; s[nt][1] = p1; s[nt][2] = p2; s[nt][3] = p3;
                l0 += p0 + p1; l1 += p2 + p3;
            }
        }

        // ---- PV: O += Ph*Vh + Pl*Vh + Ph*Vl  (x4.trans: 2 d-tiles per load)
        for (int kk = kkmin; kk < kkmax; kk++) {
            uint32_t pah[4], pal[4];
            split2(s[2 * kk][0],     s[2 * kk][1],     pah[0], pal[0]);
            split2(s[2 * kk][2],     s[2 * kk][3],     pah[1], pal[1]);
            split2(s[2 * kk + 1][0], s[2 * kk + 1][1], pah[2], pal[2]);
            split2(s[2 * kk + 1][2], s[2 * kk + 1][3], pah[3], pal[3]);
            const int vr = kk * 16 + (lane & 15);
            #pragma unroll
            for (int dt = 0; dt < 16; dt += 2) {
                const int vc = (dt + (lane >> 4)) * 8;
                uint32_t bh[4], bl[4];
                ldsm4t(db + VOFF_H + swoff(vr, vc), bh);
                ldsm4t(db + VOFF_L + swoff(vr, vc), bl);
                mma16816(o[dt],     pah, bh);
                mma16816(o[dt],     pal, bh);
                mma16816(o[dt],     pah, bl);
                mma16816(o[dt + 1], pah, bh + 2);
                mma16816(o[dt + 1], pal, bh + 2);
                mma16816(o[dt + 1], pah, bl + 2);
            }
        }
    }

    // ---- deferred row-sum reduction (quad lanes share a row)
    l0 += __shfl_xor_sync(0xffffffffu, l0, 1);
    l0 += __shfl_xor_sync(0xffffffffu, l0, 2);
    l1 += __shfl_xor_sync(0xffffffffu, l1, 1);
    l1 += __shfl_xor_sync(0xffffffffu, l1, 2);

    // ---- epilogue: normalize, store
    const float inv0 = 1.0f / l0, inv1 = 1.0f / l1;
    float* ob = O + (size_t)(lo_m + r) * QSTR + h * 128 + c2;
    #pragma unroll
    for (int dt = 0; dt < 16; dt++) {
        float2 s0, s1;
        s0.x = o[dt][0] * inv0; s0.y = o[dt][1] * inv0;
        s1.x = o[dt][2] * inv1; s1.y = o[dt][3] * inv1;
        *(float2*)(ob + dt * 8)            = s0;
        *(float2*)(ob + dt * 8 + 8 * QSTR) = s1;
    }
}

extern "C" void kernel_launch(void* const* d_in, const int* in_sizes, int n_in,
                              void* d_out, int out_size)
{
    const float* Q = (const float*)d_in[0];
    const float* K = (const float*)d_in[1];
    const float* V = (const float*)d_in[2];
    float* O = (float*)d_out;

    const int S = in_sizes[0] / QSTR;   // 2048

    prep_kv<<<(8 * 2048 * 64) / 256, 256>>>(K, V);

    cudaFuncSetAttribute(swa_mma_kernel,
                         cudaFuncAttributeMaxDynamicSharedMemorySize, SMEM_BYTES);

    dim3 grid(S / BM, 32);
    swa_mma_kernel<<<grid, NTH, SMEM_BYTES>>>(Q, O);
}

// round 17
// speedup vs baseline: 1.1999x; 1.1999x over previous
#include <cuda_runtime.h>
#include <cuda_fp16.h>
#include <cstdint>

#define WINDOW 512
#define NMETA  4
#define BM     64
#define NTH    128
#define QSTR   4096
#define KSTR   1024
#define SCALE  0.08838834764831845f

// smem: Q hi/lo fp16 [64][256B] each + two KV buffers (K,V fp16 [64][256B] each)
#define SM_QH  0
#define SM_QL  16384
#define SM_BUF 32768
#define BUF_SZ 32768
#define VOFF   16384
#define SMEM_BYTES 98304

// pre-rounded fp16 K/V scratch: [8 kv-heads][2048 rows][256 B], smem layout
__device__ __align__(16) char g_K[8 * 2048 * 256];
__device__ __align__(16) char g_V[8 * 2048 * 256];

__device__ __forceinline__ uint32_t s2u(const void* p){
    uint32_t a;
    asm("{ .reg .u64 t; cvta.to.shared.u64 t, %1; cvt.u32.u64 %0, t; }":"=r"(a):"l"(p));
    return a;
}
__device__ __forceinline__ uint32_t swoff(int row, int col){
    return (uint32_t)(row * 256 + (((col >> 3) ^ (row & 7)) << 4));
}
__device__ __forceinline__ uint32_t packh(__half a, __half b){
    return (uint32_t)__half_as_ushort(a) | ((uint32_t)__half_as_ushort(b) << 16);
}
// exact fp32 -> fp16 hi/lo split of a pair
__device__ __forceinline__ void split2h(float a, float b, uint32_t& hp, uint32_t& lp){
    __half ah = __float2half_rn(a), bh = __float2half_rn(b);
    __half al = __float2half_rn(a - __half2float(ah));
    __half bl = __float2half_rn(b - __half2float(bh));
    hp = packh(ah, bh); lp = packh(al, bl);
}
__device__ __forceinline__ void ldsm4(uint32_t a, uint32_t r[4]){
    asm volatile("ldmatrix.sync.aligned.m8n8.x4.shared.b16 {%0,%1,%2,%3},[%4];"
        : "=r"(r[0]), "=r"(r[1]), "=r"(r[2]), "=r"(r[3]) : "r"(a));
}
__device__ __forceinline__ void ldsm2(uint32_t a, uint32_t r[2]){
    asm volatile("ldmatrix.sync.aligned.m8n8.x2.shared.b16 {%0,%1},[%2];"
        : "=r"(r[0]), "=r"(r[1]) : "r"(a));
}
__device__ __forceinline__ void ldsm2t(uint32_t a, uint32_t r[2]){
    asm volatile("ldmatrix.sync.aligned.m8n8.x2.trans.shared.b16 {%0,%1},[%2];"
        : "=r"(r[0]), "=r"(r[1]) : "r"(a));
}
__device__ __forceinline__ void mma16816(float d[4], const uint32_t a[4], const uint32_t b[2]){
    asm volatile("mma.sync.aligned.m16n8k16.row.col.f32.f16.f16.f32 "
        "{%0,%1,%2,%3},{%4,%5,%6,%7},{%8,%9},{%0,%1,%2,%3};"
        : "+f"(d[0]), "+f"(d[1]), "+f"(d[2]), "+f"(d[3])
        : "r"(a[0]), "r"(a[1]), "r"(a[2]), "r"(a[3]), "r"(b[0]), "r"(b[1]));
}
#define CPA(dst, src) asm volatile("cp.async.cg.shared.global [%0],[%1],16;"::"r"(dst),"l"(src):"memory")
#define CPC()  asm volatile("cp.async.commit_group;":::"memory")
#define CPW0() asm volatile("cp.async.wait_group 0;":::"memory")
#define CPW1() asm volatile("cp.async.wait_group 1;":::"memory")

// ---- prepass: K/V fp32 -> fp16 scratch in swizzled smem-identical layout
__global__ __launch_bounds__(256)
void prep_kv(const float* __restrict__ K, const float* __restrict__ V)
{
    int idx = blockIdx.x * 256 + threadIdx.x;   // 8*2048*64 threads
    int c2 = idx & 63;
    int n  = (idx >> 6) & 2047;
    int kh = idx >> 17;
    int c  = c2 * 2;
    const float2 k2 = *(const float2*)(K + (size_t)n * KSTR + kh * 128 + c);
    const float2 v2 = *(const float2*)(V + (size_t)n * KSTR + kh * 128 + c);
    size_t off = ((size_t)kh * 2048 + n) * 256
               + (uint32_t)((((c >> 3) ^ (n & 7)) << 4) + (c & 7) * 2);
    *(uint32_t*)(g_K + off) = packh(__float2half_rn(k2.x), __float2half_rn(k2.y));
    *(uint32_t*)(g_V + off) = packh(__float2half_rn(v2.x), __float2half_rn(v2.y));
}

__global__ __launch_bounds__(NTH, 2)
void swa_mma_kernel(const float* __restrict__ Q, float* __restrict__ O)
{
    extern __shared__ char smp[];
    const uint32_t sb = s2u(smp);

    const int tid = threadIdx.x, wid = tid >> 5, lane = tid & 31;
    const int h = blockIdx.y, kh = h >> 2;
    const int i0 = ((int)gridDim.x - 1 - (int)blockIdx.x) * BM;  // heavy blocks first

    const int m0 = wid * 16;
    const int r  = lane >> 2;
    const int c2 = (lane & 3) * 2;
    const int lo_m = i0 + m0;

    const int t_lo = (i0 > WINDOW) ? ((i0 - WINDOW) >> 6) : 0;
    const int t_hi = i0 >> 6;
    const int ntiles = (t_lo == 0) ? (t_hi + 1) : (t_hi - t_lo + 2);

    auto stage = [&](int tx){
        const int t  = (t_lo == 0) ? tx : ((tx == 0) ? 0 : (t_lo + tx - 1));
        const int j0 = t << 6;
        const bool meta = (t == 0) && (t_lo >= 1);
        const size_t base = ((size_t)kh * 2048 + j0) * 256;
        const uint32_t db = sb + SM_BUF + (uint32_t)(tx & 1) * BUF_SZ;
        const int ng = meta ? 256 : 1024;        // 16 rows vs 64 rows (16B groups)
        for (int g = tid; g < ng; g += NTH) {
            uint32_t go = (uint32_t)g * 16;
            CPA(db + go,        g_K + base + go);
            CPA(db + VOFF + go, g_V + base + go);
        }
        CPC();
    };

    stage(0);

    // ---- stage Q -> fp16 hi/lo (swizzled [m][d])
    {
        const float4* Q4 = (const float4*)(Q + (size_t)i0 * QSTR + h * 128);
        #pragma unroll
        for (int it = 0; it < 16; it++) {
            int e = tid + it * NTH, m = e >> 5, c4 = e & 31, d = c4 * 4;
            float4 q = Q4[(size_t)m * (QSTR / 4) + c4];
            uint32_t h01, l01, h23, l23;
            split2h(q.x, q.y, h01, l01); split2h(q.z, q.w, h23, l23);
            uint32_t off = swoff(m, d) + (uint32_t)((d & 7) * 2);
            *(uint2*)(smp + SM_QH + off) = make_uint2(h01, h23);
            *(uint2*)(smp + SM_QL + off) = make_uint2(l01, l23);
        }
    }
    __syncthreads();

    // ---- hoist Q fragments into registers (once)
    uint32_t qh[8][4], ql[8][4];
    {
        const int ar = m0 + (lane & 7) + (lane & 8);
        #pragma unroll
        for (int ks = 0; ks < 8; ks++) {
            const int ac = ks * 16 + ((lane & 16) >> 1);
            ldsm4(sb + SM_QH + swoff(ar, ac), qh[ks]);
            ldsm4(sb + SM_QL + swoff(ar, ac), ql[ks]);
        }
    }

    float l0 = 0.f, l1 = 0.f;
    float o[16][4];
    #pragma unroll
    for (int dt = 0; dt < 16; dt++)
        #pragma unroll
        for (int e = 0; e < 4; e++) o[dt][e] = 0.f;

    for (int tix = 0; tix < ntiles; tix++) {
        const int t  = (t_lo == 0) ? tix : ((tix == 0) ? 0 : (t_lo + tix - 1));
        const int j0 = t << 6;
        const bool meta = (t == 0) && (t_lo >= 1);

        if (tix + 1 < ntiles) { stage(tix + 1); CPW1(); }
        else                  { CPW0(); }
        __syncthreads();

        const uint32_t db = sb + SM_BUF + (uint32_t)(tix & 1) * BUF_SZ;

        // two-sided window/causal block skip; tile t==0 holds sinks -> no lower skip
        const int dcl = lo_m + 15 - j0;
        int ntmin, ntmax, kkmin, kkmax;
        if (meta) { ntmin = 0; ntmax = 1; kkmin = 0; kkmax = 1; }
        else {
            ntmax = min(8, max(0, (dcl >> 3) + 1));
            kkmax = min(4, max(0, (dcl >> 4) + 1));
            if (t == 0) { ntmin = 0; kkmin = 0; }
            else {
                ntmin = max(0, (lo_m - WINDOW - j0) >> 3);
                kkmin = max(0, (lo_m - WINDOW - j0) >> 4);
            }
        }

        // ---- QK^T: S = Qh*K + Ql*K  (K already fp16; each fragment feeds 2 MMAs)
        float s[8][4];
        #pragma unroll
        for (int nt = 0; nt < 8; nt++)
            #pragma unroll
            for (int e = 0; e < 4; e++) s[nt][e] = 0.f;

        #pragma unroll
        for (int ks = 0; ks < 8; ks++) {
            const int bc = ks * 16 + (lane & 8);
            for (int nt = ntmin; nt < ntmax; nt++) {
                const int br = nt * 8 + (lane & 7);
                uint32_t bh[2];
                ldsm2(db + swoff(br, bc), bh);
                mma16816(s[nt], qh[ks], bh);
                mma16816(s[nt], ql[ks], bh);
            }
        }

        // ---- mask + static-max softmax: p = exp(s*scale)
        {
            const int i_r0 = lo_m + r, i_r1 = i_r0 + 8;
            for (int nt = ntmin; nt < ntmax; nt++) {
                const int jb = j0 + nt * 8 + c2;
                bool ok0 = (i_r0 >= jb)     && (((i_r0 - jb)     <= WINDOW) || (jb     < NMETA));
                bool ok1 = (i_r0 >= jb + 1) && (((i_r0 - jb - 1) <= WINDOW) || (jb + 1 < NMETA));
                bool ok2 = (i_r1 >= jb)     && (((i_r1 - jb)     <= WINDOW) || (jb     < NMETA));
                bool ok3 = (i_r1 >= jb + 1) && (((i_r1 - jb - 1) <= WINDOW) || (jb + 1 < NMETA));
                float p0 = ok0 ? __expf(s[nt][0] * SCALE) : 0.f;
                float p1 = ok1 ? __expf(s[nt][1] * SCALE) : 0.f;
                float p2 = ok2 ? __expf(s[nt][2] * SCALE) : 0.f;
                float p3 = ok3 ? __expf(s[nt][3] * SCALE) : 0.f;
                s[nt][0] = p0; s[nt][1] = p1; s[nt][2] = p2; s[nt][3] = p3;
                l0 += p0 + p1; l1 += p2 + p3;
            }
        }

        // ---- PV: O += Ph*V + Pl*V  (P hi/lo split in registers; V already fp16)
        for (int kk = kkmin; kk < kkmax; kk++) {
            uint32_t pah[4], pal[4];
            split2h(s[2 * kk][0],     s[2 * kk][1],     pah[0], pal[0]);
            split2h(s[2 * kk][2],     s[2 * kk][3],     pah[1], pal[1]);
            split2h(s[2 * kk + 1][0], s[2 * kk + 1][1], pah[2], pal[2]);
            split2h(s[2 * kk + 1][2], s[2 * kk + 1][3], pah[3], pal[3]);
            const int vr = kk * 16 + (lane & 15);
            #pragma unroll
            for (int dt = 0; dt < 16; dt++) {
                uint32_t bh[2];
                ldsm2t(db + VOFF + swoff(vr, dt * 8), bh);
                mma16816(o[dt], pah, bh);
                mma16816(o[dt], pal, bh);
            }
        }
        __syncthreads();   // all reads of buf[tix&1] done before tile tix+2 rewrites it
    }

    // ---- deferred row-sum reduction (quad lanes share a row)
    l0 += __shfl_xor_sync(0xffffffffu, l0, 1);
    l0 += __shfl_xor_sync(0xffffffffu, l0, 2);
    l1 += __shfl_xor_sync(0xffffffffu, l1, 1);
    l1 += __shfl_xor_sync(0xffffffffu, l1, 2);

    // ---- epilogue: normalize, store
    const float inv0 = 1.0f / l0, inv1 = 1.0f / l1;
    float* ob = O + (size_t)(lo_m + r) * QSTR + h * 128 + c2;
    #pragma unroll
    for (int dt = 0; dt < 16; dt++) {
        float2 s0, s1;
        s0.x = o[dt][0] * inv0; s0.y = o[dt][1] * inv0;
        s1.x = o[dt][2] * inv1; s1.y = o[dt][3] * inv1;
        *(float2*)(ob + dt * 8)            = s0;
        *(float2*)(ob + dt * 8 + 8 * QSTR) = s1;
    }
}

extern "C" void kernel_launch(void* const* d_in, const int* in_sizes, int n_in,
                              void* d_out, int out_size)
{
    const float* Q = (const float*)d_in[0];
    const float* K = (const float*)d_in[1];
    const float* V = (const float*)d_in[2];
    float* O = (float*)d_out;

    const int S = in_sizes[0] / QSTR;   // 2048

    prep_kv<<<(8 * 2048 * 64) / 256, 256>>>(K, V);

    cudaFuncSetAttribute(swa_mma_kernel,
                         cudaFuncAttributeMaxDynamicSharedMemorySize, SMEM_BYTES);

    dim3 grid(S / BM, 32);
    swa_mma_kernel<<<grid, NTH, SMEM_BYTES>>>(Q, O);
}